// round 3
// baseline (speedup 1.0000x reference)
#include <cuda_runtime.h>
#include <cuda_bf16.h>
#include <math.h>

typedef unsigned long long ull;

#define E_   1024
#define HID_ 1024
#define V_   32000
#define B_   32
#define S_   128
#define SB_  4096   // S_*B_
#define G4_  4096   // 4*HID_

// ---------------- device scratch (static, no allocation) ----------------
__device__ float g_Wxcat[E_ * G4_];     // [k][g*HID+j], row-major
__device__ float g_WhT[G4_ * HID_];     // [(g*HID+j)][k]  (transposed, k contiguous)
__device__ float g_bcat[G4_];
__device__ float g_Xe[SB_ * E_];        // gathered embeddings, row r = s*B+b
__device__ float g_Xpre[SB_ * G4_];     // x-side preactivations (+bias)
__device__ float g_Hall[SB_ * HID_];    // all h_t
__device__ float g_Cst[B_ * HID_];      // running cell state
__device__ int   g_is64;                // X dtype flag: 1 = int64, 0 = int32

// ---------------- f32x2 helpers (Blackwell packed fp32) ----------------
__device__ __forceinline__ ull dup_f32(float x) {
    ull r;
    asm("mov.b64 %0, {%1, %1};" : "=l"(r) : "r"(__float_as_uint(x)));
    return r;
}
__device__ __forceinline__ ull pack2(float x, float y) {
    ull r;
    asm("mov.b64 %0, {%1, %2};" : "=l"(r) : "r"(__float_as_uint(x)), "r"(__float_as_uint(y)));
    return r;
}
__device__ __forceinline__ void ffma2(ull &d, ull a, ull b) {
    asm("fma.rn.f32x2 %0, %1, %2, %0;" : "+l"(d) : "l"(a), "l"(b));
}

// ---------------- dtype detection for X ----------------
// If X is int64 (tokens < 2^31), odd 32-bit words are all 0.
// If X is int32, OR of 32 random tokens in [0,32000) is ~never 0.
__global__ void detect_kernel(const int* __restrict__ X32)
{
    if (blockIdx.x == 0 && threadIdx.x == 0) {
        int o = 0;
#pragma unroll
        for (int i = 0; i < 32; ++i) o |= X32[2 * i + 1];
        g_is64 = (o == 0) ? 1 : 0;
    }
}

// ---------------- prep: concat gate weights, transpose Wh, copy C ----------------
__global__ void prep_kernel(
    const float* __restrict__ Wxi, const float* __restrict__ Whi, const float* __restrict__ bi,
    const float* __restrict__ Wxf, const float* __restrict__ Whf, const float* __restrict__ bf,
    const float* __restrict__ Wxo, const float* __restrict__ Who, const float* __restrict__ bo,
    const float* __restrict__ Wxc, const float* __restrict__ Whc, const float* __restrict__ bc,
    const float* __restrict__ Cin)
{
    int idx = blockIdx.x * blockDim.x + threadIdx.x;   // grid covers E_*HID_
    if (idx < E_ * HID_) {
        int k = idx >> 10, j = idx & 1023;
        g_Wxcat[k * G4_ + 0 * HID_ + j] = Wxi[idx];
        g_Wxcat[k * G4_ + 1 * HID_ + j] = Wxf[idx];
        g_Wxcat[k * G4_ + 2 * HID_ + j] = Wxo[idx];
        g_Wxcat[k * G4_ + 3 * HID_ + j] = Wxc[idx];
        g_WhT[(0 * HID_ + j) * HID_ + k] = Whi[idx];
        g_WhT[(1 * HID_ + j) * HID_ + k] = Whf[idx];
        g_WhT[(2 * HID_ + j) * HID_ + k] = Who[idx];
        g_WhT[(3 * HID_ + j) * HID_ + k] = Whc[idx];
    }
    if (idx < G4_) {
        int g = idx >> 10, j = idx & 1023;
        const float* bp = (g == 0) ? bi : (g == 1) ? bf : (g == 2) ? bo : bc;
        g_bcat[idx] = bp[j];
    }
    if (idx < B_ * HID_) g_Cst[idx] = Cin[idx];
}

// ---------------- gather: Xe[r=s*B+b][:] = emb[X[b][s]][:] ----------------
__global__ void gather_kernel(const void* __restrict__ Xraw, const float* __restrict__ emb)
{
    int id = blockIdx.x * blockDim.x + threadIdx.x;    // over SB_*E_/4 float4s
    int r  = id >> 8;        // 256 float4 per row (E_=1024)
    int k4 = (id & 255) << 2;
    int s = r >> 5, b = r & 31;
    int tok;
    if (g_is64) tok = (int)((const long long*)Xraw)[b * S_ + s];
    else        tok = ((const int*)Xraw)[b * S_ + s];
    *(float4*)&g_Xe[r * E_ + k4] = *(const float4*)&emb[(size_t)tok * E_ + k4];
}

// ---------------- big SGEMM with f32x2 FMAs ----------------
// C[M,N] = A[M,K] @ B[K,N] + bias[N].  M = gridDim.y*128, N = gridDim.x*128, K % 16 == 0.
__global__ __launch_bounds__(256, 2)
void sgemm_f32x2(const float* __restrict__ A, const float* __restrict__ Bm,
                 const float* __restrict__ bias, float* __restrict__ C,
                 int N, int K)
{
    __shared__ float As[2][16][128];
    __shared__ float Bs[2][16][128];
    const int tid = threadIdx.x;
    const long rowBase = (long)blockIdx.y * 128;
    const long colBase = (long)blockIdx.x * 128;

    const int aid0 = tid, aid1 = tid + 256;
    const int ar0 = aid0 >> 2, ak0 = (aid0 & 3) << 2;
    const int ar1 = aid1 >> 2, ak1 = (aid1 & 3) << 2;
    const int bk0 = aid0 >> 5, bn0 = (aid0 & 31) << 2;
    const int bk1 = aid1 >> 5, bn1 = (aid1 & 31) << 2;

    const float* Arow0 = A + (rowBase + ar0) * (long)K;
    const float* Arow1 = A + (rowBase + ar1) * (long)K;
    const float* Bp0   = Bm + (long)bk0 * N + colBase + bn0;
    const float* Bp1   = Bm + (long)bk1 * N + colBase + bn1;

    float4 a0r = *(const float4*)(Arow0 + ak0);
    float4 a1r = *(const float4*)(Arow1 + ak1);
    float4 b0r = *(const float4*)(Bp0);
    float4 b1r = *(const float4*)(Bp1);
    As[0][ak0 + 0][ar0] = a0r.x; As[0][ak0 + 1][ar0] = a0r.y;
    As[0][ak0 + 2][ar0] = a0r.z; As[0][ak0 + 3][ar0] = a0r.w;
    As[0][ak1 + 0][ar1] = a1r.x; As[0][ak1 + 1][ar1] = a1r.y;
    As[0][ak1 + 2][ar1] = a1r.z; As[0][ak1 + 3][ar1] = a1r.w;
    *(float4*)&Bs[0][bk0][bn0] = b0r;
    *(float4*)&Bs[0][bk1][bn1] = b1r;
    __syncthreads();

    ull acc[8][4];
#pragma unroll
    for (int i = 0; i < 8; ++i)
#pragma unroll
        for (int jb = 0; jb < 4; ++jb) acc[i][jb] = 0ULL;

    const int tr = (tid >> 4) << 3;   // 0..120
    const int tc = (tid & 15) << 3;

    const int KT = K >> 4;
    for (int kt = 0; kt < KT; ++kt) {
        const int cur = kt & 1;
        if (kt + 1 < KT) {
            const int k0 = (kt + 1) << 4;
            a0r = *(const float4*)(Arow0 + k0 + ak0);
            a1r = *(const float4*)(Arow1 + k0 + ak1);
            b0r = *(const float4*)(Bp0 + (long)k0 * N);
            b1r = *(const float4*)(Bp1 + (long)k0 * N);
        }
#pragma unroll
        for (int kk = 0; kk < 16; ++kk) {
            float4 av0 = *(const float4*)&As[cur][kk][tr];
            float4 av1 = *(const float4*)&As[cur][kk][tr + 4];
            float4 bv0 = *(const float4*)&Bs[cur][kk][tc];
            float4 bv1 = *(const float4*)&Bs[cur][kk][tc + 4];
            ull bd0 = pack2(bv0.x, bv0.y), bd1 = pack2(bv0.z, bv0.w);
            ull bd2 = pack2(bv1.x, bv1.y), bd3 = pack2(bv1.z, bv1.w);
            float av[8] = {av0.x, av0.y, av0.z, av0.w, av1.x, av1.y, av1.z, av1.w};
#pragma unroll
            for (int i = 0; i < 8; ++i) {
                ull ad = dup_f32(av[i]);
                ffma2(acc[i][0], ad, bd0);
                ffma2(acc[i][1], ad, bd1);
                ffma2(acc[i][2], ad, bd2);
                ffma2(acc[i][3], ad, bd3);
            }
        }
        if (kt + 1 < KT) {
            const int nxt = cur ^ 1;
            As[nxt][ak0 + 0][ar0] = a0r.x; As[nxt][ak0 + 1][ar0] = a0r.y;
            As[nxt][ak0 + 2][ar0] = a0r.z; As[nxt][ak0 + 3][ar0] = a0r.w;
            As[nxt][ak1 + 0][ar1] = a1r.x; As[nxt][ak1 + 1][ar1] = a1r.y;
            As[nxt][ak1 + 2][ar1] = a1r.z; As[nxt][ak1 + 3][ar1] = a1r.w;
            *(float4*)&Bs[nxt][bk0][bn0] = b0r;
            *(float4*)&Bs[nxt][bk1][bn1] = b1r;
        }
        __syncthreads();
    }

    float bv[8];
#pragma unroll
    for (int j = 0; j < 8; ++j) bv[j] = bias[colBase + tc + j];
#pragma unroll
    for (int i = 0; i < 8; ++i) {
        float* crow = C + (rowBase + tr + i) * (long)N + colBase + tc;
#pragma unroll
        for (int jb = 0; jb < 4; ++jb) {
            float lo = __uint_as_float((unsigned)(acc[i][jb] & 0xffffffffULL));
            float hi = __uint_as_float((unsigned)(acc[i][jb] >> 32));
            crow[jb * 2 + 0] = lo + bv[jb * 2 + 0];
            crow[jb * 2 + 1] = hi + bv[jb * 2 + 1];
        }
    }
}

// ---------------- per-step recurrence: h@Wh (4 gates) + fused LSTM cell ----------------
__global__ __launch_bounds__(256)
void lstm_step(const float* __restrict__ Hin, int s)
{
    __shared__ float hs[32][64];
    __shared__ float ws[32][72];

    const int tid = threadIdx.x;
    const int j0 = blockIdx.x * 8;
    const int b  = tid >> 3;
    const int jj = tid & 7;
    const int j  = j0 + jj;

    const float* hprev = (s == 0) ? Hin : (g_Hall + (s - 1) * B_ * HID_);
    float* hout = g_Hall + s * B_ * HID_;

    const int xrow = (s * B_ + b) * G4_;
    float acc0 = g_Xpre[xrow + 0 * HID_ + j];
    float acc1 = g_Xpre[xrow + 1 * HID_ + j];
    float acc2 = g_Xpre[xrow + 2 * HID_ + j];
    float acc3 = g_Xpre[xrow + 3 * HID_ + j];

    for (int k0 = 0; k0 < HID_; k0 += 64) {
        __syncthreads();
        {   // load h tile: 32 x 64 floats = 512 float4, 2/thread
            int id = tid;
            *(float4*)&hs[id >> 4][(id & 15) << 2] =
                *(const float4*)&hprev[(id >> 4) * HID_ + k0 + ((id & 15) << 2)];
            id = tid + 256;
            *(float4*)&hs[id >> 4][(id & 15) << 2] =
                *(const float4*)&hprev[(id >> 4) * HID_ + k0 + ((id & 15) << 2)];
        }
        {   // load W tile: rows = g*8+jx, k contiguous (WhT)
            int id = tid;
            int row = id >> 4, kk4 = (id & 15) << 2;
            int g = row >> 3, jx = row & 7;
            *(float4*)&ws[row][kk4] =
                *(const float4*)&g_WhT[((g << 10) + j0 + jx) * HID_ + k0 + kk4];
            id = tid + 256;
            row = id >> 4; kk4 = (id & 15) << 2;
            g = row >> 3; jx = row & 7;
            *(float4*)&ws[row][kk4] =
                *(const float4*)&g_WhT[((g << 10) + j0 + jx) * HID_ + k0 + kk4];
        }
        __syncthreads();
#pragma unroll
        for (int kk = 0; kk < 64; kk += 4) {
            float4 h4 = *(const float4*)&hs[b][kk];
            float4 w0 = *(const float4*)&ws[0 * 8 + jj][kk];
            float4 w1 = *(const float4*)&ws[1 * 8 + jj][kk];
            float4 w2 = *(const float4*)&ws[2 * 8 + jj][kk];
            float4 w3 = *(const float4*)&ws[3 * 8 + jj][kk];
            acc0 = fmaf(h4.x, w0.x, acc0); acc0 = fmaf(h4.y, w0.y, acc0);
            acc0 = fmaf(h4.z, w0.z, acc0); acc0 = fmaf(h4.w, w0.w, acc0);
            acc1 = fmaf(h4.x, w1.x, acc1); acc1 = fmaf(h4.y, w1.y, acc1);
            acc1 = fmaf(h4.z, w1.z, acc1); acc1 = fmaf(h4.w, w1.w, acc1);
            acc2 = fmaf(h4.x, w2.x, acc2); acc2 = fmaf(h4.y, w2.y, acc2);
            acc2 = fmaf(h4.z, w2.z, acc2); acc2 = fmaf(h4.w, w2.w, acc2);
            acc3 = fmaf(h4.x, w3.x, acc3); acc3 = fmaf(h4.y, w3.y, acc3);
            acc3 = fmaf(h4.z, w3.z, acc3); acc3 = fmaf(h4.w, w3.w, acc3);
        }
    }

    float Ig = 1.0f / (1.0f + expf(-acc0));
    float Fg = 1.0f / (1.0f + expf(-acc1));
    float Og = 1.0f / (1.0f + expf(-acc2));
    float Ct = tanhf(acc3);
    const int cidx = b * HID_ + j;
    float c = Fg * g_Cst[cidx] + Ig * Ct;
    g_Cst[cidx] = c;
    hout[cidx] = Og * tanhf(c);
}

// ---------------- tail: Hf, Cf ----------------
__global__ void tail_kernel(float* __restrict__ out, int out_size)
{
    const long YOFF = (long)SB_ * V_;          // 131,072,000
    int idx = blockIdx.x * blockDim.x + threadIdx.x;   // 32768
    if ((long)out_size >= YOFF + 2L * B_ * HID_) {
        out[YOFF + idx] = g_Hall[(S_ - 1) * B_ * HID_ + idx];
        out[YOFF + B_ * HID_ + idx] = g_Cst[idx];
    }
}

// ---------------- launch ----------------
extern "C" void kernel_launch(void* const* d_in, const int* in_sizes, int n_in,
                              void* d_out, int out_size)
{
    const void*  X   = d_in[0];
    const float* H0  = (const float*)d_in[1];
    const float* C0  = (const float*)d_in[2];
    const float* emb = (const float*)d_in[3];
    const float* Wxi = (const float*)d_in[4];
    const float* Whi = (const float*)d_in[5];
    const float* bi  = (const float*)d_in[6];
    const float* Wxf = (const float*)d_in[7];
    const float* Whf = (const float*)d_in[8];
    const float* bf  = (const float*)d_in[9];
    const float* Wxo = (const float*)d_in[10];
    const float* Who = (const float*)d_in[11];
    const float* bo  = (const float*)d_in[12];
    const float* Wxc = (const float*)d_in[13];
    const float* Whc = (const float*)d_in[14];
    const float* bc  = (const float*)d_in[15];
    const float* Whq = (const float*)d_in[16];
    const float* bq  = (const float*)d_in[17];
    float* out = (float*)d_out;

    float *pXe, *pXpre, *pHall, *pWx, *pb;
    cudaGetSymbolAddress((void**)&pXe,   g_Xe);
    cudaGetSymbolAddress((void**)&pXpre, g_Xpre);
    cudaGetSymbolAddress((void**)&pHall, g_Hall);
    cudaGetSymbolAddress((void**)&pWx,   g_Wxcat);
    cudaGetSymbolAddress((void**)&pb,    g_bcat);

    detect_kernel<<<1, 32>>>((const int*)X);
    prep_kernel<<<4096, 256>>>(Wxi, Whi, bi, Wxf, Whf, bf,
                               Wxo, Who, bo, Wxc, Whc, bc, C0);
    gather_kernel<<<4096, 256>>>(X, emb);

    // Xpre = Xe @ Wxcat + bcat   (M=4096, N=4096, K=1024)
    sgemm_f32x2<<<dim3(32, 32), 256>>>(pXe, pWx, pb, pXpre, G4_, E_);

    // sequential recurrence
    for (int s = 0; s < S_; ++s)
        lstm_step<<<128, 256>>>(H0, s);

    // Y = Hall @ Whq + bq  (M=4096, N=32000, K=1024) -> d_out rows r = s*B+b
    sgemm_f32x2<<<dim3(V_ / 128, SB_ / 128), 256>>>(pHall, Whq, bq, out, V_, HID_);

    tail_kernel<<<128, 256>>>(out, out_size);
}

// round 8
// speedup vs baseline: 2.7417x; 2.7417x over previous
#include <cuda_runtime.h>
#include <cuda_bf16.h>
#include <math.h>

typedef unsigned long long ull;
typedef unsigned int u32;

#define E_   1024
#define HID_ 1024
#define V_   32000
#define B_   32
#define S_   128
#define SB_  4096   // S_*B_
#define G4_  4096   // 4*HID_

// ---------------- device scratch (static, no allocation) ----------------
__device__ float g_WhT[G4_ * HID_];     // [(g*HID+j)][k]  fp32, recurrence
__device__ float g_bcat[G4_];
__device__ float g_Xpre[SB_ * G4_];
__device__ float g_Hall[SB_ * HID_];
__device__ float g_Cst[B_ * HID_];
__device__ float g_Part[2][B_ * G4_];
__device__ __nv_bfloat16 g_XeHi[SB_ * E_];            // embedded inputs hi/lo
__device__ __nv_bfloat16 g_XeLo[SB_ * E_];
__device__ __nv_bfloat16 g_WxTHi[G4_ * E_];           // Wx^T [g*HID+j][k] hi/lo
__device__ __nv_bfloat16 g_WxTLo[G4_ * E_];
__device__ __nv_bfloat16 g_AHi[SB_ * HID_];           // Hall hi/lo
__device__ __nv_bfloat16 g_ALo[SB_ * HID_];
__device__ __nv_bfloat16 g_BHi[(size_t)V_ * HID_];    // Whq^T [n][k] hi/lo
__device__ __nv_bfloat16 g_BLo[(size_t)V_ * HID_];
__device__ int g_is64;

// ---------------- helpers ----------------
__device__ __forceinline__ u32 smem_u32(const void* p) {
    u32 a;
    asm("{ .reg .u64 t; cvta.to.shared.u64 t, %1; cvt.u32.u64 %0, t; }" : "=r"(a) : "l"(p));
    return a;
}
__device__ __forceinline__ ull gptr(const void* p) {
    ull g; asm("cvta.to.global.u64 %0, %1;" : "=l"(g) : "l"(p)); return g;
}
#define CPASYNC16(dst, src) \
    asm volatile("cp.async.ca.shared.global [%0], [%1], 16;" :: "r"(dst), "l"(src))
#define CP_COMMIT()  asm volatile("cp.async.commit_group;")
#define CP_WAIT(n)   asm volatile("cp.async.wait_group %0;" :: "n"(n))

#define LDSM4(r, a) \
    asm volatile("ldmatrix.sync.aligned.m8n8.x4.shared.b16 {%0,%1,%2,%3}, [%4];" \
        : "=r"((r)[0]), "=r"((r)[1]), "=r"((r)[2]), "=r"((r)[3]) : "r"(a))

__device__ __forceinline__ void mma_bf16(float* d, const u32* a, const u32* b) {
    asm volatile("mma.sync.aligned.m16n8k16.row.col.f32.bf16.bf16.f32 "
        "{%0,%1,%2,%3}, {%4,%5,%6,%7}, {%8,%9}, {%0,%1,%2,%3};"
        : "+f"(d[0]), "+f"(d[1]), "+f"(d[2]), "+f"(d[3])
        : "r"(a[0]), "r"(a[1]), "r"(a[2]), "r"(a[3]), "r"(b[0]), "r"(b[1]));
}

__device__ __forceinline__ void split_bf16(float v, __nv_bfloat16& h, __nv_bfloat16& l) {
    h = __float2bfloat16(v);
    l = __float2bfloat16(v - __bfloat162float(h));
}

// ---------------- dtype detect ----------------
__global__ void detect_kernel(const int* __restrict__ X32)
{
    if (blockIdx.x == 0 && threadIdx.x == 0) {
        int o = 0;
#pragma unroll
        for (int i = 0; i < 32; ++i) o |= X32[2 * i + 1];
        g_is64 = (o == 0) ? 1 : 0;
    }
}

// ---------------- prep: WhT fp32, WxT bf16 hi/lo, bias concat, C copy ----------------
__global__ void prep_kernel(
    const float* __restrict__ Wxi, const float* __restrict__ Whi, const float* __restrict__ bi,
    const float* __restrict__ Wxf, const float* __restrict__ Whf, const float* __restrict__ bf,
    const float* __restrict__ Wxo, const float* __restrict__ Who, const float* __restrict__ bo,
    const float* __restrict__ Wxc, const float* __restrict__ Whc, const float* __restrict__ bc,
    const float* __restrict__ Cin)
{
    int idx = blockIdx.x * blockDim.x + threadIdx.x;
    if (idx < E_ * HID_) {
        int k = idx >> 10, j = idx & 1023;
        const float* wx[4] = { Wxi, Wxf, Wxo, Wxc };
        const float* wh[4] = { Whi, Whf, Who, Whc };
#pragma unroll
        for (int g = 0; g < 4; ++g) {
            size_t r = (size_t)(g * HID_ + j);
            float xv = wx[g][idx];
            __nv_bfloat16 h, l; split_bf16(xv, h, l);
            g_WxTHi[r * E_ + k] = h;
            g_WxTLo[r * E_ + k] = l;
            g_WhT[r * HID_ + k] = wh[g][idx];
        }
    }
    if (idx < G4_) {
        int g = idx >> 10, j = idx & 1023;
        const float* bp = (g == 0) ? bi : (g == 1) ? bf : (g == 2) ? bo : bc;
        g_bcat[idx] = bp[j];
    }
    if (idx < B_ * HID_) g_Cst[idx] = Cin[idx];
}

// ---------------- gather + bf16 split: XeHi/Lo[r=s*B+b][:] = split(emb[X[b][s]]) ----------------
__global__ void gather_kernel(const void* __restrict__ Xraw, const float* __restrict__ emb)
{
    int id = blockIdx.x * blockDim.x + threadIdx.x;    // SB_*E_/4
    int r  = id >> 8;
    int k4 = (id & 255) << 2;
    int s = r >> 5, b = r & 31;
    int tok;
    if (g_is64) tok = (int)((const long long*)Xraw)[b * S_ + s];
    else        tok = ((const int*)Xraw)[b * S_ + s];
    float4 v = *(const float4*)&emb[(size_t)tok * E_ + k4];
    __nv_bfloat16 h0, l0, h1, l1, h2, l2, h3, l3;
    split_bf16(v.x, h0, l0); split_bf16(v.y, h1, l1);
    split_bf16(v.z, h2, l2); split_bf16(v.w, h3, l3);
    uint2 hp, lp;
    hp.x = (u32)__bfloat16_as_ushort(h0) | ((u32)__bfloat16_as_ushort(h1) << 16);
    hp.y = (u32)__bfloat16_as_ushort(h2) | ((u32)__bfloat16_as_ushort(h3) << 16);
    lp.x = (u32)__bfloat16_as_ushort(l0) | ((u32)__bfloat16_as_ushort(l1) << 16);
    lp.y = (u32)__bfloat16_as_ushort(l2) | ((u32)__bfloat16_as_ushort(l3) << 16);
    *(uint2*)&g_XeHi[r * E_ + k4] = hp;
    *(uint2*)&g_XeLo[r * E_ + k4] = lp;
}

// ---------------- Whq transpose + bf16 split ----------------
__global__ void wq_split(const float* __restrict__ Wq)
{
    __shared__ float t[32][33];
    int n0 = blockIdx.x * 32, k0 = blockIdx.y * 32;
    int tx = threadIdx.x, ty = threadIdx.y;   // 32 x 8
#pragma unroll
    for (int i = 0; i < 4; ++i) {
        int k = k0 + ty + i * 8;
        t[ty + i * 8][tx] = Wq[(size_t)k * V_ + n0 + tx];
    }
    __syncthreads();
#pragma unroll
    for (int i = 0; i < 4; ++i) {
        int n = n0 + ty + i * 8;
        float v = t[tx][ty + i * 8];
        __nv_bfloat16 h, l; split_bf16(v, h, l);
        g_BHi[(size_t)n * HID_ + k0 + tx] = h;
        g_BLo[(size_t)n * HID_ + k0 + tx] = l;
    }
}

// ---------------- Hall fp32 -> bf16 hi/lo ----------------
__global__ void hall_split()
{
    int i = blockIdx.x * 256 + threadIdx.x;
    float v = g_Hall[i];
    __nv_bfloat16 h, l; split_bf16(v, h, l);
    g_AHi[i] = h;
    g_ALo[i] = l;
}

// ---------------- generic split-bf16 HMMA GEMM ----------------
// C[m0+128, n0+128] = A @ B^T + bias, K = 1024.
// A stored [M][K], B stored [N][K], both as hi/lo bf16 pairs.
// 256 threads = 8 warps (4m x 2n), warp tile 32x64, K-chunks of 32, 2-stage cp.async.
#define GEMM_SMEM 81920   // 2 buffers * 4 matrices * 128 rows * 80 B
__global__ __launch_bounds__(256, 2)
void gemm_mma(const __nv_bfloat16* __restrict__ Ahi, const __nv_bfloat16* __restrict__ Alo,
              const __nv_bfloat16* __restrict__ Bhi, const __nv_bfloat16* __restrict__ Blo,
              const float* __restrict__ bias, float* __restrict__ C, int ldc)
{
    extern __shared__ __align__(128) char smraw[];
    const u32 sbase = smem_u32(smraw);
    const int tid = threadIdx.x;
    const int lane = tid & 31, wid = tid >> 5;
    const int wm = (wid & 3) * 32, wn = (wid >> 2) * 64;
    const size_t m0 = (size_t)blockIdx.x * 128, n0 = (size_t)blockIdx.y * 128;

    ull gsrc[4];
    gsrc[0] = gptr(Ahi + m0 * 1024);
    gsrc[1] = gptr(Alo + m0 * 1024);
    gsrc[2] = gptr(Bhi + n0 * 1024);
    gsrc[3] = gptr(Blo + n0 * 1024);

    const int lrow = tid >> 2;            // 0..63  (+64 on second pass)
    const int lc16 = (tid & 3) * 16;      // byte within 64B row chunk

    // per-chunk loader: 4 matrices x 128 rows x 64 B, 16B per cp.async
    auto load_chunk = [&](int ch, int buf) {
        const u32 bb = sbase + buf * 40960;
        const ull srcoff = (ull)ch * 64;  // bytes along K
#pragma unroll
        for (int mat = 0; mat < 4; ++mat) {
            const ull src = gsrc[mat] + srcoff;
            const u32 dst = bb + mat * 10240;
#pragma unroll
            for (int j = 0; j < 2; ++j) {
                int row = lrow + j * 64;
                CPASYNC16(dst + row * 80 + lc16, (const void*)(src + (ull)row * 2048 + lc16));
            }
        }
        CP_COMMIT();
    };

    float acc[2][8][4];
#pragma unroll
    for (int mf = 0; mf < 2; ++mf)
#pragma unroll
        for (int nf = 0; nf < 8; ++nf)
#pragma unroll
            for (int q = 0; q < 4; ++q) acc[mf][nf][q] = 0.0f;

    load_chunk(0, 0);

    for (int ch = 0; ch < 32; ++ch) {
        if (ch < 31) { load_chunk(ch + 1, (ch + 1) & 1); CP_WAIT(1); }
        else         { CP_WAIT(0); }
        __syncthreads();
        const u32 bb = sbase + (ch & 1) * 40960;
#pragma unroll
        for (int ks = 0; ks < 2; ++ks) {
            u32 ah[8], al[8];
            const u32 arow = wm + (lane & 15);
            const u32 acol = ks * 32 + ((lane >> 4) << 4);
            const u32 a0 = bb + arow * 80 + acol;
            const u32 a1 = bb + (arow + 16) * 80 + acol;
            LDSM4(&ah[0], a0); LDSM4(&ah[4], a1);
            LDSM4(&al[0], a0 + 10240); LDSM4(&al[4], a1 + 10240);
#pragma unroll
            for (int p = 0; p < 4; ++p) {
                u32 bh[4], bl[4];
                const u32 brow = wn + p * 16 + (lane & 7) + ((lane & 16) ? 8 : 0);
                const u32 bcol = ks * 32 + ((lane & 8) ? 16 : 0);
                const u32 ba = bb + 20480 + brow * 80 + bcol;
                LDSM4(bh, ba); LDSM4(bl, ba + 10240);
#pragma unroll
                for (int mf = 0; mf < 2; ++mf)
#pragma unroll
                    for (int sub = 0; sub < 2; ++sub) {
                        float* d = acc[mf][p * 2 + sub];
                        mma_bf16(d, &ah[mf * 4], &bh[sub * 2]);   // hi*hi
                        mma_bf16(d, &ah[mf * 4], &bl[sub * 2]);   // hi*lo
                        mma_bf16(d, &al[mf * 4], &bh[sub * 2]);   // lo*hi
                    }
            }
        }
        __syncthreads();
    }

    // epilogue: c-frag (row = lane>>2 [+8], cols = (lane&3)*2 + {0,1})
    const int r0 = lane >> 2, cp2 = (lane & 3) * 2;
#pragma unroll
    for (int mf = 0; mf < 2; ++mf) {
        const size_t row = m0 + wm + mf * 16 + r0;
#pragma unroll
        for (int nf = 0; nf < 8; ++nf) {
            const size_t col = n0 + wn + nf * 8 + cp2;
            const float b0 = bias[col], b1 = bias[col + 1];
            float2 v0 = { acc[mf][nf][0] + b0, acc[mf][nf][1] + b1 };
            float2 v1 = { acc[mf][nf][2] + b0, acc[mf][nf][3] + b1 };
            *(float2*)&C[row * (size_t)ldc + col] = v0;
            *(float2*)&C[(row + 8) * (size_t)ldc + col] = v1;
        }
    }
}

// ---------------- recurrence GEMM: partial h@Wh, k-split 2 ----------------
#define LSTM_SMEM ((2 * 32 * 68 + 2 * 64 * 68) * 4)
__global__ __launch_bounds__(128)
void lstm_gemm(const float* __restrict__ Hin, int s)
{
    extern __shared__ __align__(128) float sm[];
    float* hsm = sm;                 // [2][32*68]
    float* wsm = sm + 2 * 32 * 68;   // [2][64*68]

    const int tid = threadIdx.x;
    const int tx = tid & 15, ty = tid >> 4;
    const int ct = blockIdx.x & 63, kh = blockIdx.x >> 6;
    const int c0 = ct * 64, kbase = kh * 512;
    const float* hprev = (s == 0) ? Hin : (g_Hall + (s - 1) * B_ * HID_);

    float4 hreg[4], wreg[8];

#pragma unroll
    for (int i = 0; i < 4; ++i) {
        int idx = i * 128 + tid; int row = idx >> 4, seg = (idx & 15) << 2;
        hreg[i] = *(const float4*)&hprev[row * HID_ + kbase + seg];
    }
#pragma unroll
    for (int i = 0; i < 8; ++i) {
        int idx = i * 128 + tid; int row = idx >> 4, seg = (idx & 15) << 2;
        wreg[i] = *(const float4*)&g_WhT[(c0 + row) * HID_ + kbase + seg];
    }
#pragma unroll
    for (int i = 0; i < 4; ++i) {
        int idx = i * 128 + tid; int row = idx >> 4, seg = (idx & 15) << 2;
        *(float4*)&hsm[row * 68 + seg] = hreg[i];
    }
#pragma unroll
    for (int i = 0; i < 8; ++i) {
        int idx = i * 128 + tid; int row = idx >> 4, seg = (idx & 15) << 2;
        *(float4*)&wsm[row * 68 + seg] = wreg[i];
    }
    __syncthreads();

    float acc[4][4];
#pragma unroll
    for (int a = 0; a < 4; ++a)
#pragma unroll
        for (int b = 0; b < 4; ++b) acc[a][b] = 0.0f;

    for (int ch = 0; ch < 8; ++ch) {
        const int cur = ch & 1;
        if (ch < 7) {
            const int k0 = kbase + (ch + 1) * 64;
#pragma unroll
            for (int i = 0; i < 4; ++i) {
                int idx = i * 128 + tid; int row = idx >> 4, seg = (idx & 15) << 2;
                hreg[i] = *(const float4*)&hprev[row * HID_ + k0 + seg];
            }
#pragma unroll
            for (int i = 0; i < 8; ++i) {
                int idx = i * 128 + tid; int row = idx >> 4, seg = (idx & 15) << 2;
                wreg[i] = *(const float4*)&g_WhT[(c0 + row) * HID_ + k0 + seg];
            }
        }
        const float* hb = hsm + cur * (32 * 68);
        const float* wb = wsm + cur * (64 * 68);
#pragma unroll
        for (int kk = 0; kk < 64; kk += 4) {
            float4 hv[4], wv[4];
#pragma unroll
            for (int bb = 0; bb < 4; ++bb) hv[bb] = *(const float4*)&hb[(ty * 4 + bb) * 68 + kk];
#pragma unroll
            for (int cc = 0; cc < 4; ++cc) wv[cc] = *(const float4*)&wb[(tx + cc * 16) * 68 + kk];
#pragma unroll
            for (int bb = 0; bb < 4; ++bb)
#pragma unroll
                for (int cc = 0; cc < 4; ++cc) {
                    acc[bb][cc] = fmaf(hv[bb].x, wv[cc].x, acc[bb][cc]);
                    acc[bb][cc] = fmaf(hv[bb].y, wv[cc].y, acc[bb][cc]);
                    acc[bb][cc] = fmaf(hv[bb].z, wv[cc].z, acc[bb][cc]);
                    acc[bb][cc] = fmaf(hv[bb].w, wv[cc].w, acc[bb][cc]);
                }
        }
        if (ch < 7) {
            float* hn = hsm + (cur ^ 1) * (32 * 68);
            float* wn = wsm + (cur ^ 1) * (64 * 68);
#pragma unroll
            for (int i = 0; i < 4; ++i) {
                int idx = i * 128 + tid; int row = idx >> 4, seg = (idx & 15) << 2;
                *(float4*)&hn[row * 68 + seg] = hreg[i];
            }
#pragma unroll
            for (int i = 0; i < 8; ++i) {
                int idx = i * 128 + tid; int row = idx >> 4, seg = (idx & 15) << 2;
                *(float4*)&wn[row * 68 + seg] = wreg[i];
            }
        }
        __syncthreads();
    }

#pragma unroll
    for (int bb = 0; bb < 4; ++bb)
#pragma unroll
        for (int cc = 0; cc < 4; ++cc)
            g_Part[kh][(ty * 4 + bb) * G4_ + c0 + tx + cc * 16] = acc[bb][cc];
}

// ---------------- recurrence reduce + activations ----------------
__global__ void lstm_reduce(int s)
{
    int idx = blockIdx.x * 256 + threadIdx.x;
    int b = idx >> 10, j = idx & 1023;
    const float* xp = g_Xpre + (size_t)(s * B_ + b) * G4_;
    int pb = b * G4_ + j;
    float p0 = xp[j]        + g_Part[0][pb]        + g_Part[1][pb];
    float p1 = xp[1024 + j] + g_Part[0][pb + 1024] + g_Part[1][pb + 1024];
    float p2 = xp[2048 + j] + g_Part[0][pb + 2048] + g_Part[1][pb + 2048];
    float p3 = xp[3072 + j] + g_Part[0][pb + 3072] + g_Part[1][pb + 3072];
    float I = 1.0f / (1.0f + expf(-p0));
    float F = 1.0f / (1.0f + expf(-p1));
    float O = 1.0f / (1.0f + expf(-p2));
    float Ct = tanhf(p3);
    float c = F * g_Cst[idx] + I * Ct;
    g_Cst[idx] = c;
    g_Hall[s * B_ * HID_ + idx] = O * tanhf(c);
}

// ---------------- tail: Hf, Cf ----------------
__global__ void tail_kernel(float* __restrict__ out, int out_size)
{
    const long YOFF = (long)SB_ * V_;
    int idx = blockIdx.x * blockDim.x + threadIdx.x;
    if ((long)out_size >= YOFF + 2L * B_ * HID_) {
        out[YOFF + idx] = g_Hall[(S_ - 1) * B_ * HID_ + idx];
        out[YOFF + B_ * HID_ + idx] = g_Cst[idx];
    }
}

// ---------------- launch ----------------
extern "C" void kernel_launch(void* const* d_in, const int* in_sizes, int n_in,
                              void* d_out, int out_size)
{
    const void*  X   = d_in[0];
    const float* H0  = (const float*)d_in[1];
    const float* C0  = (const float*)d_in[2];
    const float* emb = (const float*)d_in[3];
    const float* Wxi = (const float*)d_in[4];
    const float* Whi = (const float*)d_in[5];
    const float* bi  = (const float*)d_in[6];
    const float* Wxf = (const float*)d_in[7];
    const float* Whf = (const float*)d_in[8];
    const float* bf  = (const float*)d_in[9];
    const float* Wxo = (const float*)d_in[10];
    const float* Who = (const float*)d_in[11];
    const float* bo  = (const float*)d_in[12];
    const float* Wxc = (const float*)d_in[13];
    const float* Whc = (const float*)d_in[14];
    const float* bc  = (const float*)d_in[15];
    const float* Whq = (const float*)d_in[16];
    const float* bq  = (const float*)d_in[17];
    float* out = (float*)d_out;

    void *pXeHi, *pXeLo, *pWxTHi, *pWxTLo, *pAHi, *pALo, *pBHi, *pBLo, *pb, *pXpre;
    cudaGetSymbolAddress(&pXeHi,  g_XeHi);
    cudaGetSymbolAddress(&pXeLo,  g_XeLo);
    cudaGetSymbolAddress(&pWxTHi, g_WxTHi);
    cudaGetSymbolAddress(&pWxTLo, g_WxTLo);
    cudaGetSymbolAddress(&pAHi,   g_AHi);
    cudaGetSymbolAddress(&pALo,   g_ALo);
    cudaGetSymbolAddress(&pBHi,   g_BHi);
    cudaGetSymbolAddress(&pBLo,   g_BLo);
    cudaGetSymbolAddress(&pb,     g_bcat);
    cudaGetSymbolAddress(&pXpre,  g_Xpre);

    cudaFuncSetAttribute(gemm_mma,  cudaFuncAttributeMaxDynamicSharedMemorySize, GEMM_SMEM);
    cudaFuncSetAttribute(lstm_gemm, cudaFuncAttributeMaxDynamicSharedMemorySize, LSTM_SMEM);

    detect_kernel<<<1, 32>>>((const int*)X);
    prep_kernel<<<4096, 256>>>(Wxi, Whi, bi, Wxf, Whf, bf,
                               Wxo, Who, bo, Wxc, Whc, bc, C0);
    gather_kernel<<<4096, 256>>>(X, emb);
    wq_split<<<dim3(V_ / 32, HID_ / 32), dim3(32, 8)>>>(Whq);

    // Xpre = Xe @ Wx^T + bcat   (M=4096, N=4096, K=1024)
    gemm_mma<<<dim3(SB_ / 128, G4_ / 128), 256, GEMM_SMEM>>>(
        (const __nv_bfloat16*)pXeHi, (const __nv_bfloat16*)pXeLo,
        (const __nv_bfloat16*)pWxTHi, (const __nv_bfloat16*)pWxTLo,
        (const float*)pb, (float*)pXpre, G4_);

    // sequential recurrence
    for (int s = 0; s < S_; ++s) {
        lstm_gemm<<<128, 128, LSTM_SMEM>>>(H0, s);
        lstm_reduce<<<128, 256>>>(s);
    }

    // Y = Hall @ Whq + bq  (M=4096, N=32000, K=1024)
    hall_split<<<SB_ * HID_ / 256, 256>>>();
    gemm_mma<<<dim3(SB_ / 128, V_ / 128), 256, GEMM_SMEM>>>(
        (const __nv_bfloat16*)pAHi, (const __nv_bfloat16*)pALo,
        (const __nv_bfloat16*)pBHi, (const __nv_bfloat16*)pBLo,
        bq, out, V_);

    tail_kernel<<<128, 256>>>(out, out_size);
}